// round 5
// baseline (speedup 1.0000x reference)
#include <cuda_runtime.h>
#include <cuda_bf16.h>
#include <cstdint>

// Dynamic grouped depthwise 1D conv:
//   x: [B=8, C=512, L=4096] f32
//   w: [B=8, WC=64, KS=7, L=4096] f32, groups = C/WC = 8
//   out[b,c,l] = sum_k x_pad[b,c,l+k] * w[b, c/groups, k, l],  pad = 3 (zeros)
//
// R5 (= R4 with the missing <cstdint> include): overlap the two latency legs
// that were serial in R3:
//   - x window LDGs issued FIRST (registers, used after sync)
//   - w tile staged via cp.async (LDGSTS, no landing regs) in parallel
//   - sync, then LDS w (each read feeds 2 channels) + FMA + STG
// 512 thr/block, 2 channels/thread, 1 float4 position/thread.

#define B_DIM 8
#define C_DIM 512
#define L_DIM 4096
#define WC_DIM 64
#define KS 7
#define GROUPS 8              // C / WC
#define TILE_L 512
#define TILE_F (TILE_L / 4)   // 128 float4 positions per tile
#define THREADS 512

__device__ __forceinline__ void cp_async16(unsigned int smem_addr, const void* gptr) {
    asm volatile("cp.async.cg.shared.global [%0], [%1], 16;\n"
                 :: "r"(smem_addr), "l"(gptr) : "memory");
}

__global__ __launch_bounds__(THREADS, 2)
void SKA_40106404610132_kernel(const float* __restrict__ x,
                               const float* __restrict__ w,
                               float* __restrict__ out)
{
    __shared__ float ws[KS][TILE_L];   // 14 KB

    const int tile = blockIdx.x;          // 0..7
    const int wc   = blockIdx.y;          // 0..63
    const int b    = blockIdx.z;          // 0..7
    const int l0   = tile * TILE_L;
    const int tid  = threadIdx.x;

    // ---- thread -> (position f, channel pair cq) ----
    const int f  = tid & (TILE_F - 1);    // 0..127
    const int cq = tid >> 7;              // 0..3 -> channels 2cq, 2cq+1
    const int fg = tile * TILE_F + f;     // float4 idx within row [0,1024)

    const long row0 = (long)b * C_DIM + wc * GROUPS + cq * 2;
    const float4* x0 = reinterpret_cast<const float4*>(x + row0 * L_DIM);
    const float4* x1 = reinterpret_cast<const float4*>(x + (row0 + 1) * L_DIM);

    const float4 zero4 = make_float4(0.f, 0.f, 0.f, 0.f);
    const bool has_lo = (fg > 0);
    const bool has_hi = (fg < L_DIM / 4 - 1);

    // ---- leg 1: issue 6 x-window LDG.128 now (consumed after sync) ----
    const float4 xb0 = x0[fg];
    const float4 xb1 = x1[fg];
    const float4 xa0 = has_lo ? x0[fg - 1] : zero4;
    const float4 xa1 = has_lo ? x1[fg - 1] : zero4;
    const float4 xc0 = has_hi ? x0[fg + 1] : zero4;
    const float4 xc1 = has_hi ? x1[fg + 1] : zero4;

    // ---- leg 2 (parallel): stage w tile via cp.async ----
    const float* wbase = w + (((long)b * WC_DIM + wc) * KS) * L_DIM + l0;
    {
        const unsigned int ws_base =
            (unsigned int)__cvta_generic_to_shared(&ws[0][0]);
        #pragma unroll
        for (int idx = tid; idx < KS * TILE_F; idx += THREADS) {   // <=2 iters
            const int k = idx >> 7;
            const int q = idx & (TILE_F - 1);
            cp_async16(ws_base + (unsigned int)(k * TILE_L + q * 4) * 4u,
                       wbase + (long)k * L_DIM + q * 4);
        }
        asm volatile("cp.async.commit_group;\n" ::: "memory");
        asm volatile("cp.async.wait_group 0;\n" ::: "memory");
    }
    __syncthreads();

    // ---- compute ----
    float u[10], v[10];
    u[0] = xa0.y; u[1] = xa0.z; u[2] = xa0.w;
    u[3] = xb0.x; u[4] = xb0.y; u[5] = xb0.z; u[6] = xb0.w;
    u[7] = xc0.x; u[8] = xc0.y; u[9] = xc0.z;
    v[0] = xa1.y; v[1] = xa1.z; v[2] = xa1.w;
    v[3] = xb1.x; v[4] = xb1.y; v[5] = xb1.z; v[6] = xb1.w;
    v[7] = xc1.x; v[8] = xc1.y; v[9] = xc1.z;

    float4 acc0 = zero4, acc1 = zero4;
    #pragma unroll
    for (int k = 0; k < KS; k++) {
        const float4 wv = reinterpret_cast<const float4*>(ws[k])[f];
        acc0.x = fmaf(u[k + 0], wv.x, acc0.x);
        acc0.y = fmaf(u[k + 1], wv.y, acc0.y);
        acc0.z = fmaf(u[k + 2], wv.z, acc0.z);
        acc0.w = fmaf(u[k + 3], wv.w, acc0.w);
        acc1.x = fmaf(v[k + 0], wv.x, acc1.x);
        acc1.y = fmaf(v[k + 1], wv.y, acc1.y);
        acc1.z = fmaf(v[k + 2], wv.z, acc1.z);
        acc1.w = fmaf(v[k + 3], wv.w, acc1.w);
    }

    float4* o0 = reinterpret_cast<float4*>(out + row0 * L_DIM + l0);
    float4* o1 = reinterpret_cast<float4*>(out + (row0 + 1) * L_DIM + l0);
    o0[f] = acc0;
    o1[f] = acc1;
}

extern "C" void kernel_launch(void* const* d_in, const int* in_sizes, int n_in,
                              void* d_out, int out_size) {
    const float* x = (const float*)d_in[0];  // [8, 512, 4096]
    const float* w = (const float*)d_in[1];  // [8, 64, 7, 4096]
    float* out = (float*)d_out;              // [8, 512, 4096]

    dim3 grid(L_DIM / TILE_L, WC_DIM, B_DIM);  // (8, 64, 8) = 4096 blocks
    SKA_40106404610132_kernel<<<grid, THREADS>>>(x, w, out);
}

// round 6
// speedup vs baseline: 1.3346x; 1.3346x over previous
#include <cuda_runtime.h>
#include <cuda_bf16.h>

// Dynamic grouped depthwise 1D conv:
//   x: [B=8, C=512, L=4096] f32
//   w: [B=8, WC=64, KS=7, L=4096] f32, groups = C/WC = 8
//   out[b,c,l] = sum_k x_pad[b,c,l+k] * w[b, c/groups, k, l],  pad = 3 (zeros)
//
// R6: sync-free, shared-free. One thread = one float4 position x ALL 8
// channels of its group. The 8x w-reuse lives in registers (7 w-float4
// loaded once, applied to 8 channels). Each w element is read exactly once
// chip-wide -> DRAM stays at the 187MB minimum; L1 traffic drops ~2.3x vs
// the shared-staging scheme; no __syncthreads to drain MLP.

#define B_DIM 8
#define C_DIM 512
#define L_DIM 4096
#define WC_DIM 64
#define KS 7
#define GROUPS 8              // C / WC
#define TILE_F 128            // float4 positions per block (= threads)
#define THREADS 128
#define LF (L_DIM / 4)        // 1024 float4 per row

__global__ __launch_bounds__(THREADS, 7)
void SKA_40106404610132_kernel(const float* __restrict__ x,
                               const float* __restrict__ w,
                               float* __restrict__ out)
{
    const int tile = blockIdx.x;          // 0..7
    const int wc   = blockIdx.y;          // 0..63
    const int b    = blockIdx.z;          // 0..7

    const int fg = tile * TILE_F + threadIdx.x;   // float4 idx in row [0,1024)

    // ---- load the 7 w taps for this position (read exactly once chip-wide)
    const float4* w4 = reinterpret_cast<const float4*>(
        w + (((long)b * WC_DIM + wc) * KS) * L_DIM);
    float4 wv[KS];
    #pragma unroll
    for (int k = 0; k < KS; k++) wv[k] = w4[(long)k * LF + fg];

    const float4 zero4 = make_float4(0.f, 0.f, 0.f, 0.f);
    const bool has_lo = (fg > 0);
    const bool has_hi = (fg < LF - 1);

    const long rbase = (long)b * C_DIM + wc * GROUPS;  // first channel row
    const float4* xb4 = reinterpret_cast<const float4*>(x) + rbase * LF;
    float4* ob4 = reinterpret_cast<float4*>(out) + rbase * LF;

    // ---- 4 channel pairs; fully unrolled so loads front-batch across pairs
    #pragma unroll
    for (int p = 0; p < GROUPS / 2; p++) {
        const float4* x0 = xb4 + (long)(2 * p) * LF;
        const float4* x1 = x0 + LF;

        const float4 xb0 = x0[fg];
        const float4 xb1 = x1[fg];
        const float4 xa0 = has_lo ? x0[fg - 1] : zero4;
        const float4 xa1 = has_lo ? x1[fg - 1] : zero4;
        const float4 xc0 = has_hi ? x0[fg + 1] : zero4;
        const float4 xc1 = has_hi ? x1[fg + 1] : zero4;

        // window xv[i] = x[4fg - 3 + i], i = 0..9
        float u[10], v[10];
        u[0] = xa0.y; u[1] = xa0.z; u[2] = xa0.w;
        u[3] = xb0.x; u[4] = xb0.y; u[5] = xb0.z; u[6] = xb0.w;
        u[7] = xc0.x; u[8] = xc0.y; u[9] = xc0.z;
        v[0] = xa1.y; v[1] = xa1.z; v[2] = xa1.w;
        v[3] = xb1.x; v[4] = xb1.y; v[5] = xb1.z; v[6] = xb1.w;
        v[7] = xc1.x; v[8] = xc1.y; v[9] = xc1.z;

        float4 acc0 = zero4, acc1 = zero4;
        #pragma unroll
        for (int k = 0; k < KS; k++) {
            acc0.x = fmaf(u[k + 0], wv[k].x, acc0.x);
            acc0.y = fmaf(u[k + 1], wv[k].y, acc0.y);
            acc0.z = fmaf(u[k + 2], wv[k].z, acc0.z);
            acc0.w = fmaf(u[k + 3], wv[k].w, acc0.w);
            acc1.x = fmaf(v[k + 0], wv[k].x, acc1.x);
            acc1.y = fmaf(v[k + 1], wv[k].y, acc1.y);
            acc1.z = fmaf(v[k + 2], wv[k].z, acc1.z);
            acc1.w = fmaf(v[k + 3], wv[k].w, acc1.w);
        }

        float4* o0 = ob4 + (long)(2 * p) * LF;
        o0[fg] = acc0;
        (o0 + LF)[fg] = acc1;
    }
}

extern "C" void kernel_launch(void* const* d_in, const int* in_sizes, int n_in,
                              void* d_out, int out_size) {
    const float* x = (const float*)d_in[0];  // [8, 512, 4096]
    const float* w = (const float*)d_in[1];  // [8, 64, 7, 4096]
    float* out = (float*)d_out;              // [8, 512, 4096]

    dim3 grid(L_DIM / (TILE_F * 4), WC_DIM, B_DIM);  // (8, 64, 8) = 4096 blocks
    SKA_40106404610132_kernel<<<grid, THREADS>>>(x, w, out);
}